// round 2
// baseline (speedup 1.0000x reference)
#include <cuda_runtime.h>
#include <math.h>

#define N_ 128
#define H_ 256
#define B_ 16

// -------- device scratch --------
__device__ float g_P[H_*H_];        // W1^T W1
__device__ float g_Q[H_*H_];        // W2 W2^T
__device__ float g_W2T[N_*H_];      // W2T[i*H+h] = W2[h*N+i]
__device__ float g_s[B_*H_];
__device__ float g_c[B_*H_];
__device__ float g_Avec[B_*N_];
__device__ float g_Cvec[B_*N_];
__device__ float g_vn[B_];
__device__ float g_U[B_*H_*N_];     // U = P S W2   [256,128] per sample
__device__ float g_A2[B_*H_*H_];    // A2 = U W2^T  [256,256] per sample
__device__ float g_part1[B_*8];     // Term1 tile partials
__device__ float g_part2[B_*16];    // Term2 tile partials

#define MICRO_LOOP(As, Bs)                                          \
    _Pragma("unroll")                                               \
    for (int a = 0; a < 16; a++){                                   \
        float ra[4], rb[4];                                         \
        _Pragma("unroll") for (int i = 0; i < 4; i++) ra[i] = As[a][ty*4+i]; \
        _Pragma("unroll") for (int j = 0; j < 4; j++) rb[j] = Bs[a][tx*4+j]; \
        _Pragma("unroll") for (int i = 0; i < 4; i++)               \
            _Pragma("unroll") for (int j = 0; j < 4; j++)           \
                acc[i][j] += ra[i]*rb[j];                           \
    }

// -------- kernel 0: P = W1^T W1, Q = W2 W2^T, W2T (fused) --------
__global__ void k_prep(const float* __restrict__ W1, const float* __restrict__ W2){
    int z = blockIdx.z;
    int tid = threadIdx.x;
    if (z == 2){
        // transpose W2 -> W2T via 32x32 smem tiles; 16 blocks cover 4x8 tiles x2 reps
        __shared__ float ts[32][33];
        int tb = blockIdx.y*4 + blockIdx.x;
        int i0 = (tb & 3) * 32;
        int r = tid >> 5, c = tid & 31;
        for (int rep = 0; rep < 2; rep++){
            int h0 = ((tb >> 2) + rep*4) * 32;
            #pragma unroll
            for (int rr = r; rr < 32; rr += 8)
                ts[c][rr] = W2[(h0+rr)*N_ + i0 + c];
            __syncthreads();
            #pragma unroll
            for (int rr = r; rr < 32; rr += 8)
                g_W2T[(i0+rr)*H_ + h0 + c] = ts[rr][c];
            __syncthreads();
        }
        return;
    }
    __shared__ float As[16][65];
    __shared__ float Bs[16][65];
    int g0 = blockIdx.y*64, h0 = blockIdx.x*64;
    int ty = tid>>4, tx = tid&15;
    float acc[4][4];
    #pragma unroll
    for (int i = 0; i < 4; i++)
        #pragma unroll
        for (int j = 0; j < 4; j++) acc[i][j] = 0.f;

    for (int a0 = 0; a0 < N_; a0 += 16){
        if (z == 0){   // P: K-dim = rows of W1 (coalesced a-major)
            #pragma unroll
            for (int it = 0; it < 4; it++){
                int l = tid + it*256; int a = l>>6, gg = l&63;
                As[a][gg] = W1[(a0+a)*H_ + g0+gg];
                Bs[a][gg] = W1[(a0+a)*H_ + h0+gg];
            }
        } else {       // Q: K-dim = cols of W2 (k-minor)
            #pragma unroll
            for (int it = 0; it < 4; it++){
                int l = tid + it*256; int gg = l>>4, k = l&15;
                As[k][gg] = W2[(g0+gg)*N_ + a0+k];
                Bs[k][gg] = W2[(h0+gg)*N_ + a0+k];
            }
        }
        __syncthreads();
        MICRO_LOOP(As, Bs)
        __syncthreads();
    }
    float* dst = (z == 0) ? g_P : g_Q;
    #pragma unroll
    for (int i = 0; i < 4; i++)
        #pragma unroll
        for (int j = 0; j < 4; j++)
            dst[(g0+ty*4+i)*H_ + h0 + tx*4+j] = acc[i][j];
}

// -------- kernel 1: per-sample vectors (1024 threads, 4 per output) --------
__global__ void k_vectors(const float* __restrict__ tptr,
                          const float* __restrict__ state,
                          const float* __restrict__ x0,
                          const float* __restrict__ x1,
                          const float* __restrict__ W1,
                          const float* __restrict__ b1){
    int b = blockIdx.x, tid = threadIdx.x;
    __shared__ float xs[N_], vs[N_], red[N_];
    __shared__ float swv[H_], cwy[H_], pvs[H_], cwz[H_];

    float tval = *tptr;
    float window = 4.f * tval * (1.f - tval);
    if (tid < N_){
        float dev = state[b*N_ + tid];
        float v   = state[(B_+b)*N_ + tid];
        float x0v = x0[b*N_ + tid];
        xs[tid] = x0v + tval*(x1[b*N_ + tid] - x0v) + window*dev;
        vs[tid] = v;
        red[tid] = v*v;
    }
    __syncthreads();

    // ||v|| by warp 0 (no extra barrier needed; only written to gmem)
    if (tid < 32){
        float a0 = red[tid] + red[tid+32] + red[tid+64] + red[tid+96];
        #pragma unroll
        for (int o = 16; o; o >>= 1) a0 += __shfl_xor_sync(0xffffffffu, a0, o);
        if (tid == 0) g_vn[b] = sqrtf(a0);
    }

    // phase 1: u, y, w  (h = tid>>2, quarter-K per lane)
    int h = tid >> 2, q = tid & 3;
    {
        int k0 = q*32;
        float u = 0.f, y = 0.f, w = 0.f;
        #pragma unroll 8
        for (int j = 0; j < 32; j++){
            int k = k0 + j;
            float xv = xs[k], vv = vs[k];
            float w1 = W1[k*H_ + h];
            u += xv*w1;
            y += vv*w1;
            w += g_W2T[k*H_ + h]*vv;
        }
        u += __shfl_xor_sync(0xffffffffu, u, 1); u += __shfl_xor_sync(0xffffffffu, u, 2);
        y += __shfl_xor_sync(0xffffffffu, y, 1); y += __shfl_xor_sync(0xffffffffu, y, 2);
        w += __shfl_xor_sync(0xffffffffu, w, 1); w += __shfl_xor_sync(0xffffffffu, w, 2);
        float th = tanhf(u + b1[h]);
        float s = 1.f - th*th;
        float c = -2.f*th*s;
        if (q == 0){
            g_s[b*H_ + h] = s;
            g_c[b*H_ + h] = c;
            swv[h] = s*w;
            cwy[h] = c*w*y;
        }
        __syncthreads();

        // phase 2: z = P(s.w), q2 = P(c.w.y)
        int a0 = q*64;
        float z = 0.f, q2 = 0.f;
        #pragma unroll 8
        for (int j = 0; j < 64; j++){
            int a = a0 + j;
            float pa = g_P[a*H_ + h];   // P symmetric
            z  += pa*swv[a];
            q2 += pa*cwy[a];
        }
        z  += __shfl_xor_sync(0xffffffffu, z, 1);  z  += __shfl_xor_sync(0xffffffffu, z, 2);
        q2 += __shfl_xor_sync(0xffffffffu, q2, 1); q2 += __shfl_xor_sync(0xffffffffu, q2, 2);
        if (q == 0){
            pvs[h] = c*y*z + s*q2;
            cwz[h] = c*w*z;
        }
    }
    __syncthreads();

    // phase 3: A = W2^T pv, C = 2 W1 cwz  (i = 0..127, 4 lanes each)
    if (tid < 4*N_){
        int i = tid >> 2, qq = tid & 3;
        int h0 = qq*64;
        float A = 0.f, C = 0.f;
        #pragma unroll 8
        for (int j = 0; j < 64; j++){
            int hh = h0 + j;
            A += g_W2T[i*H_ + hh]*pvs[hh];
            C += W1[i*H_ + hh]*cwz[hh];
        }
        A += __shfl_xor_sync(0xffffffffu, A, 1); A += __shfl_xor_sync(0xffffffffu, A, 2);
        C += __shfl_xor_sync(0xffffffffu, C, 1); C += __shfl_xor_sync(0xffffffffu, C, 2);
        if (qq == 0){
            g_Avec[b*N_ + i] = A;
            g_Cvec[b*N_ + i] = 2.f*C;
        }
    }
}

// -------- kernel 2: U_b = P diag(s_b) W2   [256,128] --------
__global__ void k_U(const float* __restrict__ W2){
    int b = blockIdx.z;
    int g0 = blockIdx.y*64, n0 = blockIdx.x*64;
    int tid = threadIdx.x;
    int ty = tid>>4, tx = tid&15;
    __shared__ float As[16][65];
    __shared__ float Bs[16][65];
    __shared__ float ssm[H_];
    ssm[tid] = g_s[b*H_ + tid];
    __syncthreads();

    float acc[4][4];
    #pragma unroll
    for (int i = 0; i < 4; i++)
        #pragma unroll
        for (int j = 0; j < 4; j++) acc[i][j] = 0.f;

    for (int a0 = 0; a0 < H_; a0 += 16){
        #pragma unroll
        for (int it = 0; it < 4; it++){
            int l = tid + it*256; int a = l>>6, gg = l&63;
            As[a][gg] = g_P[(a0+a)*H_ + g0+gg];                 // P symmetric
            Bs[a][gg] = W2[(a0+a)*N_ + n0+gg] * ssm[a0+a];
        }
        __syncthreads();
        MICRO_LOOP(As, Bs)
        __syncthreads();
    }
    float* dst = g_U + b*H_*N_;
    #pragma unroll
    for (int i = 0; i < 4; i++)
        #pragma unroll
        for (int j = 0; j < 4; j++)
            dst[(g0+ty*4+i)*N_ + n0 + tx*4+j] = acc[i][j];
}

// -------- kernel 3: fused  A2 = U W2^T  and  Term1 = <V, K V>  --------
__global__ void k_WA(const float* __restrict__ W2){
    int b = blockIdx.z;
    int tid = threadIdx.x;
    int ty = tid>>4, tx = tid&15;
    __shared__ float As[16][65];
    __shared__ float Bs[16][65];
    __shared__ float csm[H_];
    __shared__ float red[256];

    float acc[4][4];
    #pragma unroll
    for (int i = 0; i < 4; i++)
        #pragma unroll
        for (int j = 0; j < 4; j++) acc[i][j] = 0.f;

    if (blockIdx.y < 4){
        // A2[g,h] = sum_k U[g,k] W2[h,k]    K = 128
        int g0 = blockIdx.y*64, h0 = blockIdx.x*64;
        const float* Ub = g_U + b*H_*N_;
        for (int a0 = 0; a0 < N_; a0 += 16){
            #pragma unroll
            for (int it = 0; it < 4; it++){
                int l = tid + it*256; int gg = l>>4, k = l&15;
                As[k][gg] = Ub[(g0+gg)*N_ + a0+k];
                Bs[k][gg] = W2[(h0+gg)*N_ + a0+k];
            }
            __syncthreads();
            MICRO_LOOP(As, Bs)
            __syncthreads();
        }
        float* dst = g_A2 + b*H_*H_;
        #pragma unroll
        for (int i = 0; i < 4; i++)
            #pragma unroll
            for (int j = 0; j < 4; j++)
                dst[(g0+ty*4+i)*H_ + h0 + tx*4+j] = acc[i][j];
    } else {
        // W[g,n] = sum_a (P∘Q)[g,a] c[a] U[a,n];  partial = sum W[g,n]*c[g]*U[g,n]
        int g0 = blockIdx.x*64, n0 = (blockIdx.y-4)*64;
        const float* Ub = g_U + b*H_*N_;
        csm[tid] = g_c[b*H_ + tid];
        __syncthreads();
        for (int a0 = 0; a0 < H_; a0 += 16){
            #pragma unroll
            for (int it = 0; it < 4; it++){
                int l = tid + it*256; int a = l>>6, gg = l&63;
                float p = g_P[(a0+a)*H_ + g0+gg];
                float qv = g_Q[(a0+a)*H_ + g0+gg];
                As[a][gg] = p*qv;                                  // K symmetric
                Bs[a][gg] = Ub[(a0+a)*N_ + n0+gg] * csm[a0+a];
            }
            __syncthreads();
            MICRO_LOOP(As, Bs)
            __syncthreads();
        }
        float local = 0.f;
        #pragma unroll
        for (int i = 0; i < 4; i++){
            int g = g0 + ty*4 + i;
            float cg = csm[g];
            #pragma unroll
            for (int j = 0; j < 4; j++){
                int n = n0 + tx*4 + j;
                local += acc[i][j] * cg * Ub[g*N_ + n];
            }
        }
        red[tid] = local;
        __syncthreads();
        for (int st = 128; st > 0; st >>= 1){
            if (tid < st) red[tid] += red[tid + st];
            __syncthreads();
        }
        if (tid == 0) g_part1[b*8 + blockIdx.x*2 + (blockIdx.y-4)] = red[0];
    }
}

// -------- kernel 4: Term2 = sum c_g c_h P_gh A2_gh A2_hg  (tiled, smem transpose) --------
__global__ void k_red(){
    int b = blockIdx.y;
    int gb0 = blockIdx.x*16;
    int tid = threadIdx.x;
    __shared__ float rs[16][257];   // A2[gb0+g, h]
    __shared__ float cs[256][17];   // A2[h, gb0+g]
    __shared__ float red[256];
    const float* A2b = g_A2 + b*H_*H_;
    #pragma unroll
    for (int it = 0; it < 16; it++){
        int l = tid + it*256;
        {   int gg = l>>8, h = l&255;
            rs[gg][h] = A2b[(gb0+gg)*H_ + h]; }
        {   int h = l>>4, k = l&15;
            cs[h][k] = A2b[h*H_ + gb0+k]; }
    }
    __syncthreads();

    int h = tid;
    float ch = g_c[b*H_ + h];
    float local = 0.f;
    #pragma unroll
    for (int g = 0; g < 16; g++){
        float cg = g_c[b*H_ + gb0+g];
        float pg = g_P[(gb0+g)*H_ + h];
        local += cg*ch*pg * rs[g][h] * cs[h][g];
    }
    red[tid] = local;
    __syncthreads();
    for (int st = 128; st > 0; st >>= 1){
        if (tid < st) red[tid] += red[tid + st];
        __syncthreads();
    }
    if (tid == 0) g_part2[b*16 + blockIdx.x] = red[0];
}

// -------- kernel 5: finalize --------
__global__ void k_final(const float* __restrict__ state, float* __restrict__ out){
    int b = blockIdx.x, tid = threadIdx.x;   // 128 threads
    __shared__ float nrm_s;
    if (tid == 0){
        float t1 = 0.f, t2 = 0.f;
        #pragma unroll
        for (int i = 0; i < 8; i++)  t1 += g_part1[b*8 + i];
        #pragma unroll
        for (int i = 0; i < 16; i++) t2 += g_part2[b*16 + i];
        nrm_s = sqrtf(fmaxf(2.f*(t1 + t2), 0.f));
    }
    __syncthreads();
    float nrm = nrm_s;
    float vn  = g_vn[b];
    float v   = state[(B_+b)*N_ + tid];
    float dev = state[b*N_ + tid];
    float a = -(g_Avec[b*N_ + tid] - 0.5f*g_Cvec[b*N_ + tid])
              / ((nrm + 1e-6f) * (vn + 1e-6f));
    out[b*N_ + tid]       = v;
    out[(B_+b)*N_ + tid]  = a - 0.1f*dev;
}

// -------- launch --------
extern "C" void kernel_launch(void* const* d_in, const int* in_sizes, int n_in,
                              void* d_out, int out_size){
    const float* t     = (const float*)d_in[0];
    const float* state = (const float*)d_in[1];
    const float* x0    = (const float*)d_in[2];
    const float* x1    = (const float*)d_in[3];
    const float* W1    = (const float*)d_in[4];
    const float* b1    = (const float*)d_in[5];
    const float* W2    = (const float*)d_in[6];
    float* out = (float*)d_out;

    k_prep   <<<dim3(4,4,3),  256>>>(W1, W2);
    k_vectors<<<B_,           1024>>>(t, state, x0, x1, W1, b1);
    k_U      <<<dim3(2,4,B_), 256>>>(W2);
    k_WA     <<<dim3(4,6,B_), 256>>>(W2);
    k_red    <<<dim3(16,B_),  256>>>();
    k_final  <<<B_,           N_>>>(state, out);
}

// round 3
// speedup vs baseline: 1.0502x; 1.0502x over previous
#include <cuda_runtime.h>
#include <math.h>

#define N_ 128
#define H_ 256
#define B_ 16

// -------- device scratch --------
__device__ float g_P[H_*H_];        // W1^T W1
__device__ float g_Q[H_*H_];        // W2 W2^T
__device__ float g_W2T[N_*H_];      // W2T[i*H+h] = W2[h*N+i]
__device__ float g_s[B_*H_];
__device__ float g_c[B_*H_];
__device__ float g_Avec[B_*N_];
__device__ float g_Cvec[B_*N_];
__device__ float g_vn[B_];
__device__ float g_A2[B_*H_*H_];    // A2 = P S Q per sample
__device__ float g_part[B_*8];      // nrm^2/2 tile partials (6 used)

// -------- kernel 0: P = W1^T W1, Q = W2 W2^T, W2T --------
__global__ void k_prep(const float* __restrict__ W1, const float* __restrict__ W2){
    int z = blockIdx.z;
    int tid = threadIdx.x;
    if (z == 2){
        __shared__ float ts[32][33];
        int tb = blockIdx.y*4 + blockIdx.x;
        int i0 = (tb & 3) * 32;
        int r = tid >> 5, c = tid & 31;
        for (int rep = 0; rep < 2; rep++){
            int h0 = ((tb >> 2) + rep*4) * 32;
            #pragma unroll
            for (int rr = r; rr < 32; rr += 8)
                ts[c][rr] = W2[(h0+rr)*N_ + i0 + c];
            __syncthreads();
            #pragma unroll
            for (int rr = r; rr < 32; rr += 8)
                g_W2T[(i0+rr)*H_ + h0 + c] = ts[rr][c];
            __syncthreads();
        }
        return;
    }
    __shared__ float As[16][65];
    __shared__ float Bs[16][65];
    int g0 = blockIdx.y*64, h0 = blockIdx.x*64;
    int ty = tid>>4, tx = tid&15;
    float acc[4][4];
    #pragma unroll
    for (int i = 0; i < 4; i++)
        #pragma unroll
        for (int j = 0; j < 4; j++) acc[i][j] = 0.f;

    for (int a0 = 0; a0 < N_; a0 += 16){
        if (z == 0){
            #pragma unroll
            for (int it = 0; it < 4; it++){
                int l = tid + it*256; int a = l>>6, gg = l&63;
                As[a][gg] = W1[(a0+a)*H_ + g0+gg];
                Bs[a][gg] = W1[(a0+a)*H_ + h0+gg];
            }
        } else {
            #pragma unroll
            for (int it = 0; it < 4; it++){
                int l = tid + it*256; int gg = l>>4, k = l&15;
                As[k][gg] = W2[(g0+gg)*N_ + a0+k];
                Bs[k][gg] = W2[(h0+gg)*N_ + a0+k];
            }
        }
        __syncthreads();
        #pragma unroll
        for (int a = 0; a < 16; a++){
            float ra[4], rb[4];
            #pragma unroll
            for (int i = 0; i < 4; i++) ra[i] = As[a][ty*4+i];
            #pragma unroll
            for (int j = 0; j < 4; j++) rb[j] = Bs[a][tx*4+j];
            #pragma unroll
            for (int i = 0; i < 4; i++)
                #pragma unroll
                for (int j = 0; j < 4; j++) acc[i][j] += ra[i]*rb[j];
        }
        __syncthreads();
    }
    float* dst = (z == 0) ? g_P : g_Q;
    #pragma unroll
    for (int i = 0; i < 4; i++)
        #pragma unroll
        for (int j = 0; j < 4; j++)
            dst[(g0+ty*4+i)*H_ + h0 + tx*4+j] = acc[i][j];
}

// -------- kernel 1: per-sample vectors (1024 threads, 4 per output) --------
__global__ void k_vectors(const float* __restrict__ tptr,
                          const float* __restrict__ state,
                          const float* __restrict__ x0,
                          const float* __restrict__ x1,
                          const float* __restrict__ W1,
                          const float* __restrict__ b1){
    int b = blockIdx.x, tid = threadIdx.x;
    __shared__ float xs[N_], vs[N_], red[N_];
    __shared__ float swv[H_], cwy[H_], pvs[H_], cwz[H_];

    float tval = *tptr;
    float window = 4.f * tval * (1.f - tval);
    if (tid < N_){
        float dev = state[b*N_ + tid];
        float v   = state[(B_+b)*N_ + tid];
        float x0v = x0[b*N_ + tid];
        xs[tid] = x0v + tval*(x1[b*N_ + tid] - x0v) + window*dev;
        vs[tid] = v;
        red[tid] = v*v;
    }
    __syncthreads();

    if (tid < 32){
        float a0 = red[tid] + red[tid+32] + red[tid+64] + red[tid+96];
        #pragma unroll
        for (int o = 16; o; o >>= 1) a0 += __shfl_xor_sync(0xffffffffu, a0, o);
        if (tid == 0) g_vn[b] = sqrtf(a0);
    }

    int h = tid >> 2, q = tid & 3;
    {
        int k0 = q*32;
        float u = 0.f, y = 0.f, w = 0.f;
        #pragma unroll 8
        for (int j = 0; j < 32; j++){
            int k = k0 + j;
            float xv = xs[k], vv = vs[k];
            float w1 = W1[k*H_ + h];
            u += xv*w1;
            y += vv*w1;
            w += g_W2T[k*H_ + h]*vv;
        }
        u += __shfl_xor_sync(0xffffffffu, u, 1); u += __shfl_xor_sync(0xffffffffu, u, 2);
        y += __shfl_xor_sync(0xffffffffu, y, 1); y += __shfl_xor_sync(0xffffffffu, y, 2);
        w += __shfl_xor_sync(0xffffffffu, w, 1); w += __shfl_xor_sync(0xffffffffu, w, 2);
        float th = tanhf(u + b1[h]);
        float s = 1.f - th*th;
        float c = -2.f*th*s;
        if (q == 0){
            g_s[b*H_ + h] = s;
            g_c[b*H_ + h] = c;
            swv[h] = s*w;
            cwy[h] = c*w*y;
        }
        __syncthreads();

        int a0 = q*64;
        float z = 0.f, q2 = 0.f;
        #pragma unroll 8
        for (int j = 0; j < 64; j++){
            int a = a0 + j;
            float pa = g_P[a*H_ + h];
            z  += pa*swv[a];
            q2 += pa*cwy[a];
        }
        z  += __shfl_xor_sync(0xffffffffu, z, 1);  z  += __shfl_xor_sync(0xffffffffu, z, 2);
        q2 += __shfl_xor_sync(0xffffffffu, q2, 1); q2 += __shfl_xor_sync(0xffffffffu, q2, 2);
        if (q == 0){
            pvs[h] = c*y*z + s*q2;
            cwz[h] = c*w*z;
        }
    }
    __syncthreads();

    if (tid < 4*N_){
        int i = tid >> 2, qq = tid & 3;
        int h0 = qq*64;
        float A = 0.f, C = 0.f;
        #pragma unroll 8
        for (int j = 0; j < 64; j++){
            int hh = h0 + j;
            A += g_W2T[i*H_ + hh]*pvs[hh];
            C += W1[i*H_ + hh]*cwz[hh];
        }
        A += __shfl_xor_sync(0xffffffffu, A, 1); A += __shfl_xor_sync(0xffffffffu, A, 2);
        C += __shfl_xor_sync(0xffffffffu, C, 1); C += __shfl_xor_sync(0xffffffffu, C, 2);
        if (qq == 0){
            g_Avec[b*N_ + i] = A;
            g_Cvec[b*N_ + i] = 2.f*C;
        }
    }
}

// -------- kernel 2: A2[b] = P * diag(s_b) * Q  (128x64 tiles, 8x4 micro) --------
__global__ void k_A2(){
    int b  = blockIdx.z;
    int g0 = blockIdx.y*128, h0 = blockIdx.x*64;
    int tid = threadIdx.x;
    int ty = tid >> 4, tx = tid & 15;
    __shared__ float Ps[16][132];
    __shared__ float Qs[16][68];
    float acc[8][4];
    #pragma unroll
    for (int i = 0; i < 8; i++)
        #pragma unroll
        for (int j = 0; j < 4; j++) acc[i][j] = 0.f;

    const float* sb = g_s + b*H_;
    for (int a0 = 0; a0 < H_; a0 += 16){
        #pragma unroll
        for (int it = 0; it < 8; it++){
            int l = tid + it*256; int a = l>>7, gg = l&127;
            Ps[a][gg] = g_P[(a0+a)*H_ + g0 + gg];          // P symmetric
        }
        #pragma unroll
        for (int it = 0; it < 4; it++){
            int l = tid + it*256; int a = l>>6, hh = l&63;
            Qs[a][hh] = g_Q[(a0+a)*H_ + h0 + hh] * sb[a0+a];
        }
        __syncthreads();
        #pragma unroll
        for (int a = 0; a < 16; a++){
            float ra[8], rb[4];
            *(float4*)&ra[0] = *(const float4*)&Ps[a][ty*8];
            *(float4*)&ra[4] = *(const float4*)&Ps[a][ty*8+4];
            *(float4*)&rb[0] = *(const float4*)&Qs[a][tx*4];
            #pragma unroll
            for (int i = 0; i < 8; i++)
                #pragma unroll
                for (int j = 0; j < 4; j++) acc[i][j] += ra[i]*rb[j];
        }
        __syncthreads();
    }
    float* dst = g_A2 + b*H_*H_;
    #pragma unroll
    for (int i = 0; i < 8; i++){
        int g = g0 + ty*8 + i;
        *(float4*)&dst[g*H_ + h0 + tx*4] = *(float4*)&acc[i][0];
    }
}

// -------- kernel 3: fused A1 = A2 S P + weighted symmetric reduction --------
// summand c_g c_h P_gh (Q_gh A1_gh + A2_gh A2_hg) is (g,h)-symmetric:
// compute 6/8 tiles, weight 2 above diagonal, 1 on it, 0 below.
__global__ void k_nrm(){
    int b = blockIdx.z;
    const int gy_t[6] = {0,0,0,0,1,1};
    const int hx_t[6] = {0,1,2,3,2,3};
    int g0 = gy_t[blockIdx.x]*128, h0 = hx_t[blockIdx.x]*64;
    int tid = threadIdx.x;
    int ty = tid >> 4, tx = tid & 15;
    __shared__ float As[16][132];
    __shared__ float Bs[16][68];
    float acc[8][4];
    #pragma unroll
    for (int i = 0; i < 8; i++)
        #pragma unroll
        for (int j = 0; j < 4; j++) acc[i][j] = 0.f;

    const float* A2b = g_A2 + b*H_*H_;
    const float* sb  = g_s + b*H_;
    for (int a0 = 0; a0 < H_; a0 += 16){
        #pragma unroll
        for (int it = 0; it < 8; it++){
            int l = tid + it*256; int gg = l>>4, a = l&15;
            As[a][gg] = A2b[(g0+gg)*H_ + a0 + a] * sb[a0+a];
        }
        #pragma unroll
        for (int it = 0; it < 4; it++){
            int l = tid + it*256; int a = l>>6, hh = l&63;
            Bs[a][hh] = g_P[(a0+a)*H_ + h0 + hh];
        }
        __syncthreads();
        #pragma unroll
        for (int a = 0; a < 16; a++){
            float ra[8], rb[4];
            *(float4*)&ra[0] = *(const float4*)&As[a][ty*8];
            *(float4*)&ra[4] = *(const float4*)&As[a][ty*8+4];
            *(float4*)&rb[0] = *(const float4*)&Bs[a][tx*4];
            #pragma unroll
            for (int i = 0; i < 8; i++)
                #pragma unroll
                for (int j = 0; j < 4; j++) acc[i][j] += ra[i]*rb[j];
        }
        __syncthreads();
    }

    const float* cb = g_c + b*H_;
    float local = 0.f;
    #pragma unroll
    for (int i = 0; i < 8; i++){
        int g = g0 + ty*8 + i;
        float cg = cb[g];
        #pragma unroll
        for (int j = 0; j < 4; j++){
            int h = h0 + tx*4 + j;
            float wgt = (h > g) ? 2.f : ((h == g) ? 1.f : 0.f);
            if (wgt != 0.f){
                float pg  = g_P[g*H_ + h];
                float qg  = g_Q[g*H_ + h];
                float a2  = A2b[g*H_ + h];
                float a2t = A2b[h*H_ + g];
                local += wgt*cg*cb[h]*pg*(qg*acc[i][j] + a2*a2t);
            }
        }
    }
    __shared__ float red[256];
    red[tid] = local;
    __syncthreads();
    for (int st = 128; st > 0; st >>= 1){
        if (tid < st) red[tid] += red[tid + st];
        __syncthreads();
    }
    if (tid == 0) g_part[b*8 + blockIdx.x] = red[0];
}

// -------- kernel 4: finalize --------
__global__ void k_final(const float* __restrict__ state, float* __restrict__ out){
    int b = blockIdx.x, tid = threadIdx.x;   // 128 threads
    __shared__ float nrm_s;
    if (tid == 0){
        float sum = 0.f;
        #pragma unroll
        for (int i = 0; i < 6; i++) sum += g_part[b*8 + i];
        nrm_s = sqrtf(fmaxf(2.f*sum, 0.f));
    }
    __syncthreads();
    float nrm = nrm_s;
    float vn  = g_vn[b];
    float v   = state[(B_+b)*N_ + tid];
    float dev = state[b*N_ + tid];
    float a = -(g_Avec[b*N_ + tid] - 0.5f*g_Cvec[b*N_ + tid])
              / ((nrm + 1e-6f) * (vn + 1e-6f));
    out[b*N_ + tid]       = v;
    out[(B_+b)*N_ + tid]  = a - 0.1f*dev;
}

// -------- launch --------
extern "C" void kernel_launch(void* const* d_in, const int* in_sizes, int n_in,
                              void* d_out, int out_size){
    const float* t     = (const float*)d_in[0];
    const float* state = (const float*)d_in[1];
    const float* x0    = (const float*)d_in[2];
    const float* x1    = (const float*)d_in[3];
    const float* W1    = (const float*)d_in[4];
    const float* b1    = (const float*)d_in[5];
    const float* W2    = (const float*)d_in[6];
    float* out = (float*)d_out;

    k_prep   <<<dim3(4,4,3),  256>>>(W1, W2);
    k_vectors<<<B_,           1024>>>(t, state, x0, x1, W1, b1);
    k_A2     <<<dim3(4,2,B_), 256>>>();
    k_nrm    <<<dim3(6,1,B_), 256>>>();
    k_final  <<<B_,           N_>>>(state, out);
}